// round 1
// baseline (speedup 1.0000x reference)
#include <cuda_runtime.h>
#include <math.h>

typedef unsigned long long ull;

#define BATCH 512
#define CIN   64
#define LIN   1024
#define COUTC 256
#define K1    32
#define STR1  16
#define TT    63
#define NCLS  2
#define KTOT  2048   // CIN*K1

// ---------------- device scratch (no allocation allowed) ----------------
__device__ float g_z1[BATCH * TT * COUTC];     // [n][t][co]  ~33 MB
__device__ float g_c1wt[KTOT * COUTC];         // [(ci*32+k)][co]
__device__ float g_c2wt[COUTC * 3 * COUTC];    // [(ci*3+k)][co]
__device__ float g_d1wt[COUTC * COUTC];        // [c][o]
__device__ float g_bn1a[COUTC];
__device__ float g_bn2a[COUTC];

// ---------------- packed fp32x2 helpers (IEEE fp32 per lane) ----------------
__device__ __forceinline__ ull pk2(float lo, float hi) {
    ull r; asm("mov.b64 %0, {%1,%2};" : "=l"(r) : "f"(lo), "f"(hi)); return r;
}
__device__ __forceinline__ ull fma2(ull a, ull b, ull c) {
    ull d; asm("fma.rn.f32x2 %0, %1, %2, %3;" : "=l"(d) : "l"(a), "l"(b), "l"(c)); return d;
}
__device__ __forceinline__ float2 upk2(ull v) {
    float2 f; asm("mov.b64 {%0,%1}, %2;" : "=f"(f.x), "=f"(f.y) : "l"(v)); return f;
}

// ---------------- prep: weight transposes + BN scales ----------------
__global__ void prep_kernel(const float* __restrict__ c1w,
                            const float* __restrict__ c2w,
                            const float* __restrict__ d1w,
                            const float* __restrict__ bn1g, const float* __restrict__ bn1v,
                            const float* __restrict__ bn2g, const float* __restrict__ bn2v)
{
    int i = blockIdx.x * blockDim.x + threadIdx.x;
    if (i < KTOT * COUTC) {                       // conv1 w: [o][i][k] -> [(i*32+k)][o]
        int row = i >> 8, co = i & 255;
        int ci = row >> 5, k = row & 31;
        g_c1wt[i] = c1w[(co * CIN + ci) * K1 + k];
    }
    if (i < COUTC * 3 * COUTC) {                  // conv2 w: [o][i][k] -> [(i*3+k)][o]
        int row = i >> 8, co = i & 255;
        int ci = row / 3, k = row - 3 * ci;
        g_c2wt[i] = c2w[(co * COUTC + ci) * 3 + k];
    }
    if (i < COUTC * COUTC) {                      // dense w1: [o][c] -> [c][o]
        int c = i >> 8, o = i & 255;
        g_d1wt[i] = d1w[o * COUTC + c];
    }
    if (i < COUTC) {
        g_bn1a[i] = bn1g[i] / sqrtf(bn1v[i] + 1e-5f);
        g_bn2a[i] = bn2g[i] / sqrtf(bn2v[i] + 1e-5f);
    }
}

// ---------------- conv1 (im2col GEMM, M=32256 K=2048 N=256) + BN1 ----------------
__global__ __launch_bounds__(256, 2)
void conv1_gemm(const float* __restrict__ x,
                const float* __restrict__ c1b,
                const float* __restrict__ bn1b,
                const float* __restrict__ bn1m)
{
    __shared__ __align__(16) float As[16][128];
    __shared__ __align__(16) float Bs[16][128];
    const int tid = threadIdx.x;
    const int mBase = blockIdx.x * 128;
    const int nBase = blockIdx.y * 128;

    // A-load geometry: thread covers row r0, 8 consecutive k-cols (c40..c40+7)
    const int q0  = tid * 2;
    const int r0  = q0 >> 2;               // 0..127
    const int c40 = (q0 & 3) * 4;          // 0 or 8
    {
        // hoist (n,t) decomposition of the im2col row
    }
    const int m0 = mBase + r0;
    const int n_idx = m0 / TT;
    const int t_idx = m0 - n_idx * TT;
    const float* xrow = x + ((size_t)n_idx * CIN) * LIN + t_idx * STR1;

    // B-load geometry
    const int bk0 = q0 >> 5;               // 0..15
    const int bn4 = (q0 & 31) * 4;         // multiple of 8

    ull acc[8][4];
    #pragma unroll
    for (int i = 0; i < 8; i++)
        #pragma unroll
        for (int j = 0; j < 4; j++) acc[i][j] = 0ULL;

    const int tm = (tid >> 4) * 8;
    const int tn = (tid & 15) * 8;

    for (int kb = 0; kb < KTOT; kb += 16) {
        // load A tile (im2col on the fly; contiguous along k inside one ci)
        {
            int col = kb + c40;
            int ci = col >> 5, kk = col & 31;
            float4 v = *(const float4*)(xrow + (size_t)ci * LIN + kk);
            As[c40 + 0][r0] = v.x; As[c40 + 1][r0] = v.y;
            As[c40 + 2][r0] = v.z; As[c40 + 3][r0] = v.w;
            col = kb + c40 + 4;
            ci = col >> 5; kk = col & 31;
            v = *(const float4*)(xrow + (size_t)ci * LIN + kk);
            As[c40 + 4][r0] = v.x; As[c40 + 5][r0] = v.y;
            As[c40 + 6][r0] = v.z; As[c40 + 7][r0] = v.w;
        }
        // load B tile
        {
            const float* bsrc = g_c1wt + (size_t)(kb + bk0) * COUTC + nBase + bn4;
            *(float4*)&Bs[bk0][bn4]     = *(const float4*)(bsrc);
            *(float4*)&Bs[bk0][bn4 + 4] = *(const float4*)(bsrc + 4);
        }
        __syncthreads();
        #pragma unroll
        for (int kk = 0; kk < 16; kk++) {
            float4 a0 = *(const float4*)&As[kk][tm];
            float4 a1 = *(const float4*)&As[kk][tm + 4];
            ull b0 = *(const ull*)&Bs[kk][tn];
            ull b1 = *(const ull*)&Bs[kk][tn + 2];
            ull b2 = *(const ull*)&Bs[kk][tn + 4];
            ull b3 = *(const ull*)&Bs[kk][tn + 6];
            float av[8] = {a0.x, a0.y, a0.z, a0.w, a1.x, a1.y, a1.z, a1.w};
            #pragma unroll
            for (int i = 0; i < 8; i++) {
                ull ap = pk2(av[i], av[i]);
                acc[i][0] = fma2(ap, b0, acc[i][0]);
                acc[i][1] = fma2(ap, b1, acc[i][1]);
                acc[i][2] = fma2(ap, b2, acc[i][2]);
                acc[i][3] = fma2(ap, b3, acc[i][3]);
            }
        }
        __syncthreads();
    }

    // epilogue: bias + BN1 exactly as JAX:  ((conv + b) - m) * scale + beta
    #pragma unroll
    for (int i = 0; i < 8; i++) {
        int m = mBase + tm + i;
        float o_[8];
        #pragma unroll
        for (int j = 0; j < 4; j++) {
            float2 v = upk2(acc[i][j]);
            o_[2 * j] = v.x; o_[2 * j + 1] = v.y;
        }
        #pragma unroll
        for (int jj = 0; jj < 8; jj++) {
            int co = nBase + tn + jj;
            float t1 = (o_[jj] + c1b[co]) - bn1m[co];
            o_[jj] = fmaf(t1, g_bn1a[co], bn1b[co]);
        }
        float* dst = g_z1 + (size_t)m * COUTC + nBase + tn;
        *(float4*)dst       = make_float4(o_[0], o_[1], o_[2], o_[3]);
        *(float4*)(dst + 4) = make_float4(o_[4], o_[5], o_[6], o_[7]);
    }
}

// ---------------- mega kernel: conv2+BN2 -> LIF -> dense1 -> LIF -> dense2 -> LIF ----
__global__ __launch_bounds__(512, 1)
void mega_kernel(const float* __restrict__ c2b,
                 const float* __restrict__ bn2b,
                 const float* __restrict__ bn2m,
                 const float* __restrict__ d2w,
                 float* __restrict__ out)
{
    extern __shared__ float sm[];
    float* zin  = sm;            // [t][ci]  63*256 floats (later reused as D1[o][t])
    float* bufA = sm + TT * COUTC; // [co][t]  256*63 floats

    const int n = blockIdx.x;
    const int tid = threadIdx.x;

    // load z1[n] (contiguous 16128 floats)
    {
        const float4* src = (const float4*)(g_z1 + (size_t)n * (TT * COUTC));
        float4* dstv = (float4*)zin;
        for (int i = tid; i < (TT * COUTC) / 4; i += 512) dstv[i] = src[i];
    }
    __syncthreads();

    // ---- conv2 (k=3, pad=1, stride 1) + BN2, f32x2 over t-pairs ----
    {
        const int cog = tid & 127;           // handles co = cog and cog+128
        const int th  = tid >> 7;            // 0..3 -> 16-t chunk
        const int t0  = th * 16;
        ull acc0[8], acc1[8];
        #pragma unroll
        for (int p = 0; p < 8; p++) { acc0[p] = 0ULL; acc1[p] = 0ULL; }

        for (int ci = 0; ci < COUTC; ci++) {
            const float* wp = g_c2wt + ci * 3 * COUTC;
            float w0a = wp[cog],             w1a = wp[COUTC + cog],       w2a = wp[2 * COUTC + cog];
            float w0b = wp[cog + 128],       w1b = wp[COUTC + cog + 128], w2b = wp[2 * COUTC + cog + 128];

            float zr[18];                    // z[t0-1 .. t0+16], zero-padded
            #pragma unroll
            for (int jj = 0; jj < 18; jj++) {
                int tp = t0 - 1 + jj;
                zr[jj] = (tp >= 0 && tp < TT) ? zin[tp * COUTC + ci] : 0.0f;
            }
            ull zp[9], zo[8];
            #pragma unroll
            for (int p = 0; p < 9; p++) zp[p] = pk2(zr[2 * p], zr[2 * p + 1]);
            #pragma unroll
            for (int p = 0; p < 8; p++) zo[p] = pk2(zr[2 * p + 1], zr[2 * p + 2]);
            ull w0ap = pk2(w0a, w0a), w1ap = pk2(w1a, w1a), w2ap = pk2(w2a, w2a);
            ull w0bp = pk2(w0b, w0b), w1bp = pk2(w1b, w1b), w2bp = pk2(w2b, w2b);
            #pragma unroll
            for (int p = 0; p < 8; p++) {
                acc0[p] = fma2(w0ap, zp[p],     acc0[p]);
                acc0[p] = fma2(w1ap, zo[p],     acc0[p]);
                acc0[p] = fma2(w2ap, zp[p + 1], acc0[p]);
                acc1[p] = fma2(w0bp, zp[p],     acc1[p]);
                acc1[p] = fma2(w1bp, zo[p],     acc1[p]);
                acc1[p] = fma2(w2bp, zp[p + 1], acc1[p]);
            }
        }
        // epilogue BN2: ((conv + b) - m) * scale + beta
        const int coA = cog, coB = cog + 128;
        const float cbA = c2b[coA], mA = bn2m[coA], sA = g_bn2a[coA], bA = bn2b[coA];
        const float cbB = c2b[coB], mB = bn2m[coB], sB = g_bn2a[coB], bB = bn2b[coB];
        #pragma unroll
        for (int p = 0; p < 8; p++) {
            float2 va = upk2(acc0[p]);
            float2 vb = upk2(acc1[p]);
            int t = t0 + 2 * p;
            bufA[coA * TT + t] = fmaf((va.x + cbA) - mA, sA, bA);
            bufA[coB * TT + t] = fmaf((vb.x + cbB) - mB, sB, bB);
            if (t + 1 < TT) {
                bufA[coA * TT + t + 1] = fmaf((va.y + cbA) - mA, sA, bA);
                bufA[coB * TT + t + 1] = fmaf((vb.y + cbB) - mB, sB, bB);
            }
        }
    }
    __syncthreads();

    // ---- encoder CUBA LIF: threshold 0.3, current_decay 0.9, voltage_decay 0.9 ----
    if (tid < COUTC) {
        float* row = bufA + tid * TT;
        const float cd = (float)(1.0 - 0.9);   // matches Python-double -> f32
        const float vd = (float)(1.0 - 0.9);
        float cur = 0.0f, vol = 0.0f;
        #pragma unroll 1
        for (int t = 0; t < TT; t++) {
            float xv = row[t];
            cur = fmaf(cd, cur, xv);
            vol = fmaf(vd, vol, cur);
            float s = ((vol - 0.3f) >= 0.0f) ? 1.0f : 0.0f;
            row[t] = s;
            vol = vol * (1.0f - s);
        }
    }
    __syncthreads();

    // ---- dense1: D1[o][t] = sum_c w1[o][c]*s1[c][t]  (into reused zin region) ----
    {
        const int og = tid & 127;
        const int th = tid >> 7;
        const int t0 = th * 16;
        ull acc0[8], acc1[8];
        #pragma unroll
        for (int p = 0; p < 8; p++) { acc0[p] = 0ULL; acc1[p] = 0ULL; }

        for (int c = 0; c < COUTC; c++) {
            float wa = g_d1wt[c * COUTC + og];
            float wb = g_d1wt[c * COUTC + og + 128];
            float sr[16];
            #pragma unroll
            for (int j = 0; j < 16; j++) {
                int t = t0 + j;
                sr[j] = (t < TT) ? bufA[c * TT + t] : 0.0f;
            }
            ull wap = pk2(wa, wa), wbp = pk2(wb, wb);
            #pragma unroll
            for (int p = 0; p < 8; p++) {
                ull sp = pk2(sr[2 * p], sr[2 * p + 1]);
                acc0[p] = fma2(wap, sp, acc0[p]);
                acc1[p] = fma2(wbp, sp, acc1[p]);
            }
        }
        #pragma unroll
        for (int p = 0; p < 8; p++) {
            float2 va = upk2(acc0[p]), vb = upk2(acc1[p]);
            int t = t0 + 2 * p;
            zin[og * TT + t] = va.x;
            zin[(og + 128) * TT + t] = vb.x;
            if (t + 1 < TT) {
                zin[og * TT + t + 1] = va.y;
                zin[(og + 128) * TT + t + 1] = vb.y;
            }
        }
    }
    __syncthreads();

    // ---- dense1 CUBA LIF: threshold 0.1, cd=1.0 (i=x), vd=0.1 (v = 0.9v + x) ----
    if (tid < COUTC) {
        float* row = zin + tid * TT;
        const float vdD = (float)(1.0 - 0.1);  // 0.9f
        float vol = 0.0f;
        #pragma unroll 1
        for (int t = 0; t < TT; t++) {
            float xv = row[t];
            vol = fmaf(vdD, vol, xv);
            float s = ((vol - 0.1f) >= 0.0f) ? 1.0f : 0.0f;
            row[t] = s;
            vol = vol * (1.0f - s);
        }
    }
    __syncthreads();

    // ---- dense2: [2 x 256] x s2 ----
    if (tid < NCLS * TT) {
        int cls = tid / TT, t = tid - cls * TT;
        const float* w = d2w + cls * COUTC;
        float a = 0.0f;
        #pragma unroll 4
        for (int c = 0; c < COUTC; c++) a = fmaf(w[c], zin[c * TT + t], a);
        bufA[tid] = a;
    }
    __syncthreads();

    // ---- dense2 CUBA LIF + write output [n][cls][t] ----
    if (tid < NCLS) {
        const float vdD = (float)(1.0 - 0.1);
        float vol = 0.0f;
        const float* rowi = bufA + tid * TT;
        float* rowo = out + (size_t)n * (NCLS * TT) + tid * TT;
        #pragma unroll 1
        for (int t = 0; t < TT; t++) {
            float xv = rowi[t];
            vol = fmaf(vdD, vol, xv);
            float s = ((vol - 0.1f) >= 0.0f) ? 1.0f : 0.0f;
            rowo[t] = s;
            vol = vol * (1.0f - s);
        }
    }
}

// ---------------- launch ----------------
extern "C" void kernel_launch(void* const* d_in, const int* in_sizes, int n_in,
                              void* d_out, int out_size)
{
    const float* x    = (const float*)d_in[0];
    const float* c1w  = (const float*)d_in[1];
    const float* c1b  = (const float*)d_in[2];
    const float* bn1g = (const float*)d_in[3];
    const float* bn1b = (const float*)d_in[4];
    const float* bn1m = (const float*)d_in[5];
    const float* bn1v = (const float*)d_in[6];
    const float* c2w  = (const float*)d_in[7];
    const float* c2b  = (const float*)d_in[8];
    const float* bn2g = (const float*)d_in[9];
    const float* bn2b = (const float*)d_in[10];
    const float* bn2m = (const float*)d_in[11];
    const float* bn2v = (const float*)d_in[12];
    const float* d1w  = (const float*)d_in[13];
    const float* d2w  = (const float*)d_in[14];
    float* out = (float*)d_out;

    cudaFuncSetAttribute(mega_kernel, cudaFuncAttributeMaxDynamicSharedMemorySize,
                         2 * TT * COUTC * (int)sizeof(float));

    prep_kernel<<<2048, 256>>>(c1w, c2w, d1w, bn1g, bn1v, bn2g, bn2v);

    dim3 g1(252, 2);
    conv1_gemm<<<g1, 256>>>(x, c1b, bn1b, bn1m);

    mega_kernel<<<BATCH, 512, 2 * TT * COUTC * (int)sizeof(float)>>>(
        c2b, bn2b, bn2m, d2w, out);
}

// round 2
// speedup vs baseline: 1.1164x; 1.1164x over previous
#include <cuda_runtime.h>
#include <math.h>

typedef unsigned long long ull;

#define BATCH 512
#define CIN   64
#define LIN   1024
#define COUTC 256
#define K1    32
#define STR1  16
#define TT    63
#define NCLS  2
#define KTOT  2048   // CIN*K1

#define ZROWS 66     // zin rows: t = -1 .. 64  (row = t+1)
#define BSTR  66     // bufA / d1 row stride (even -> LDS.64 pairs, 2-way conflict on scans)

// ---------------- device scratch ----------------
__device__ float g_z1[BATCH * TT * COUTC];       // [n][t][co]
__device__ float g_c1wt[KTOT * COUTC];           // [(ci*32+k)][co]
__device__ float g_c2wt[COUTC * 3 * COUTC];      // [(ci*3+k)][2*cog+half]  (co pairs interleaved)
__device__ float g_d1wt[COUTC * COUTC];          // [c][o]
__device__ float g_bn1a[COUTC];
__device__ float g_bn2a[COUTC];

// ---------------- packed fp32x2 helpers (IEEE fp32 per lane) ----------------
__device__ __forceinline__ ull pk2(float lo, float hi) {
    ull r; asm("mov.b64 %0, {%1,%2};" : "=l"(r) : "f"(lo), "f"(hi)); return r;
}
__device__ __forceinline__ ull fma2(ull a, ull b, ull c) {
    ull d; asm("fma.rn.f32x2 %0, %1, %2, %3;" : "=l"(d) : "l"(a), "l"(b), "l"(c)); return d;
}
__device__ __forceinline__ float2 upk2(ull v) {
    float2 f; asm("mov.b64 {%0,%1}, %2;" : "=f"(f.x), "=f"(f.y) : "l"(v)); return f;
}

// ---------------- prep: weight transposes + BN scales ----------------
__global__ void prep_kernel(const float* __restrict__ c1w,
                            const float* __restrict__ c2w,
                            const float* __restrict__ d1w,
                            const float* __restrict__ bn1g, const float* __restrict__ bn1v,
                            const float* __restrict__ bn2g, const float* __restrict__ bn2v)
{
    int i = blockIdx.x * blockDim.x + threadIdx.x;
    if (i < KTOT * COUTC) {                       // conv1 w: [o][i][k] -> [(i*32+k)][o]
        int row = i >> 8, co = i & 255;
        int ci = row >> 5, k = row & 31;
        g_c1wt[i] = c1w[(co * CIN + ci) * K1 + k];
    }
    if (i < COUTC * 3 * COUTC) {                  // conv2 w: pair-interleaved
        int row = i >> 8, j = i & 255;
        int ci = row / 3, k = row - 3 * ci;
        int co = (j >> 1) + 128 * (j & 1);
        g_c2wt[i] = c2w[(co * COUTC + ci) * 3 + k];
    }
    if (i < COUTC * COUTC) {                      // dense w1: [o][c] -> [c][o]
        int c = i >> 8, o = i & 255;
        g_d1wt[i] = d1w[o * COUTC + c];
    }
    if (i < COUTC) {
        g_bn1a[i] = bn1g[i] / sqrtf(bn1v[i] + 1e-5f);
        g_bn2a[i] = bn2g[i] / sqrtf(bn2v[i] + 1e-5f);
    }
}

// ---------------- conv1 (im2col GEMM, M=32256 K=2048 N=256) + BN1 ----------------
__global__ __launch_bounds__(256, 2)
void conv1_gemm(const float* __restrict__ x,
                const float* __restrict__ c1b,
                const float* __restrict__ bn1b,
                const float* __restrict__ bn1m)
{
    __shared__ __align__(16) float As[2][16][128];
    __shared__ __align__(16) float Bs[2][16][128];
    const int tid = threadIdx.x;
    const int mBase = blockIdx.x * 128;
    const int nBase = blockIdx.y * 128;

    // loader geometry
    const int q0  = tid * 2;
    const int r0  = q0 >> 2;               // A row 0..127
    const int c40 = (q0 & 3) * 4;          // 0 or 8
    const int m0 = mBase + r0;
    const int n_idx = m0 / TT;
    const int t_idx = m0 - n_idx * TT;
    const float* xrow = x + ((size_t)n_idx * CIN) * LIN + t_idx * STR1;
    const int bk0 = q0 >> 5;               // 0..15
    const int bn4 = (q0 & 31) * 4;         // multiple of 8

    const int tm = (tid >> 4) * 8;
    const int tn = (tid & 15) * 8;

    ull acc[8][4];
    #pragma unroll
    for (int i = 0; i < 8; i++)
        #pragma unroll
        for (int j = 0; j < 4; j++) acc[i][j] = 0ULL;

    float4 apf0, apf1, bpf0, bpf1;

    // ---- prefetch helpers (inline) ----
    #define LOAD_REGS(KB) {                                                   \
        int col = (KB) + c40;                                                 \
        apf0 = *(const float4*)(xrow + (size_t)(col >> 5) * LIN + (col & 31));\
        col += 4;                                                             \
        apf1 = *(const float4*)(xrow + (size_t)(col >> 5) * LIN + (col & 31));\
        const float* bsrc = g_c1wt + (size_t)((KB) + bk0) * COUTC + nBase + bn4; \
        bpf0 = *(const float4*)(bsrc);                                        \
        bpf1 = *(const float4*)(bsrc + 4);                                    \
    }
    #define STORE_SMEM(B) {                                                   \
        As[B][c40 + 0][r0] = apf0.x; As[B][c40 + 1][r0] = apf0.y;             \
        As[B][c40 + 2][r0] = apf0.z; As[B][c40 + 3][r0] = apf0.w;             \
        As[B][c40 + 4][r0] = apf1.x; As[B][c40 + 5][r0] = apf1.y;             \
        As[B][c40 + 6][r0] = apf1.z; As[B][c40 + 7][r0] = apf1.w;             \
        *(float4*)&Bs[B][bk0][bn4]     = bpf0;                                \
        *(float4*)&Bs[B][bk0][bn4 + 4] = bpf1;                                \
    }

    LOAD_REGS(0);
    STORE_SMEM(0);
    __syncthreads();

    int buf = 0;
    for (int kb = 0; kb < KTOT; kb += 16) {
        const bool more = (kb + 16) < KTOT;
        if (more) LOAD_REGS(kb + 16);

        const float (*A)[128] = As[buf];
        const float (*B)[128] = Bs[buf];
        #pragma unroll
        for (int kk = 0; kk < 16; kk++) {
            float4 a0 = *(const float4*)&A[kk][tm];
            float4 a1 = *(const float4*)&A[kk][tm + 4];
            ulonglong2 p0 = *(const ulonglong2*)&B[kk][tn];
            ulonglong2 p1 = *(const ulonglong2*)&B[kk][tn + 4];
            ull b0 = p0.x, b1 = p0.y, b2 = p1.x, b3 = p1.y;
            ull ap;
            #define FMA_ROW(I, AV)                                \
                ap = pk2(AV, AV);                                 \
                acc[I][0] = fma2(ap, b0, acc[I][0]);              \
                acc[I][1] = fma2(ap, b1, acc[I][1]);              \
                acc[I][2] = fma2(ap, b2, acc[I][2]);              \
                acc[I][3] = fma2(ap, b3, acc[I][3]);
            FMA_ROW(0, a0.x) FMA_ROW(1, a0.y) FMA_ROW(2, a0.z) FMA_ROW(3, a0.w)
            FMA_ROW(4, a1.x) FMA_ROW(5, a1.y) FMA_ROW(6, a1.z) FMA_ROW(7, a1.w)
            #undef FMA_ROW
        }
        if (more) STORE_SMEM(buf ^ 1);
        __syncthreads();
        buf ^= 1;
    }
    #undef LOAD_REGS
    #undef STORE_SMEM

    // epilogue: ((conv + b) - m) * scale + beta  -> g_z1 [n][t][co]
    #pragma unroll
    for (int i = 0; i < 8; i++) {
        int m = mBase + tm + i;
        float o_[8];
        #pragma unroll
        for (int j = 0; j < 4; j++) {
            float2 v = upk2(acc[i][j]);
            o_[2 * j] = v.x; o_[2 * j + 1] = v.y;
        }
        #pragma unroll
        for (int jj = 0; jj < 8; jj++) {
            int co = nBase + tn + jj;
            float t1 = (o_[jj] + c1b[co]) - bn1m[co];
            o_[jj] = fmaf(t1, g_bn1a[co], bn1b[co]);
        }
        float* dst = g_z1 + (size_t)m * COUTC + nBase + tn;
        *(float4*)dst       = make_float4(o_[0], o_[1], o_[2], o_[3]);
        *(float4*)(dst + 4) = make_float4(o_[4], o_[5], o_[6], o_[7]);
    }
}

// ---------------- mega kernel ----------------
__global__ __launch_bounds__(512, 1)
void mega_kernel(const float* __restrict__ c2b,
                 const float* __restrict__ bn2b,
                 const float* __restrict__ bn2m,
                 const float* __restrict__ d2w,
                 float* __restrict__ out)
{
    extern __shared__ float sm[];
    float* zin  = sm;                       // [t+1][256], rows 0..65 (rows 0,64,65 zero)
    float* bufA = sm + ZROWS * COUTC;       // [co][BSTR]

    const int n = blockIdx.x;
    const int tid = threadIdx.x;

    // ---- load z1[n] into rows 1..63; zero pad rows 0,64,65 ----
    {
        float4* z4 = (float4*)zin;
        for (int i = tid; i < COUTC / 4; i += 512) z4[i] = make_float4(0, 0, 0, 0);
        float4* zp4 = (float4*)(zin + 64 * COUTC);
        for (int i = tid; i < (2 * COUTC) / 4; i += 512) zp4[i] = make_float4(0, 0, 0, 0);
        const float4* src = (const float4*)(g_z1 + (size_t)n * (TT * COUTC));
        float4* dstv = (float4*)(zin + COUTC);
        for (int i = tid; i < (TT * COUTC) / 4; i += 512) dstv[i] = src[i];
    }
    __syncthreads();

    // ---- conv2 (k=3,p=1) + BN2 : fp32x2 lanes = (co, co+128) ----
    {
        const int cog = tid & 127;
        const int th  = tid >> 7;
        const int t0  = th * 16;
        ull acc[16];
        #pragma unroll
        for (int t = 0; t < 16; t++) acc[t] = 0ULL;

        const float* zbase = zin + t0 * COUTC;   // + jj*256 + ci covers t = t0-1 .. t0+16
        const ull* wbase = (const ull*)g_c2wt;

        for (int ci = 0; ci < COUTC; ci++) {
            ull w0 = wbase[(ci * 3 + 0) * 128 + cog];
            ull w1 = wbase[(ci * 3 + 1) * 128 + cog];
            ull w2 = wbase[(ci * 3 + 2) * 128 + cog];
            ull zz[18];
            #pragma unroll
            for (int j = 0; j < 18; j++) {
                float z = zbase[j * COUTC + ci];
                zz[j] = pk2(z, z);
            }
            #pragma unroll
            for (int t = 0; t < 16; t++) {
                acc[t] = fma2(w0, zz[t],     acc[t]);
                acc[t] = fma2(w1, zz[t + 1], acc[t]);
                acc[t] = fma2(w2, zz[t + 2], acc[t]);
            }
        }
        // BN2: ((conv + b) - m) * scale + beta
        const int coA = cog, coB = cog + 128;
        const float cbA = c2b[coA], mA = bn2m[coA], sA = g_bn2a[coA], bA = bn2b[coA];
        const float cbB = c2b[coB], mB = bn2m[coB], sB = g_bn2a[coB], bB = bn2b[coB];
        #pragma unroll
        for (int t = 0; t < 16; t++) {
            float2 v = upk2(acc[t]);
            int tt = t0 + t;                     // tt==63 writes a finite dummy (never read as spike)
            bufA[coA * BSTR + tt] = fmaf((v.x + cbA) - mA, sA, bA);
            bufA[coB * BSTR + tt] = fmaf((v.y + cbB) - mB, sB, bB);
        }
    }
    __syncthreads();

    // ---- encoder CUBA LIF: thr 0.3, cd 0.9, vd 0.9 ----
    if (tid < COUTC) {
        float* row = bufA + tid * BSTR;
        const float cd = (float)(1.0 - 0.9);
        const float vd = (float)(1.0 - 0.9);
        float cur = 0.0f, vol = 0.0f;
        #pragma unroll 1
        for (int t = 0; t < TT; t++) {
            float xv = row[t];
            cur = fmaf(cd, cur, xv);
            vol = fmaf(vd, vol, cur);
            float s = ((vol - 0.3f) >= 0.0f) ? 1.0f : 0.0f;
            row[t] = s;
            vol = vol * (1.0f - s);
        }
        row[TT] = 0.0f;                          // clean pad so dense1's last pair hi-lane is 0
    }
    __syncthreads();

    // ---- dense1: fp32x2 lanes = t-pairs, direct LDS.64 operands ----
    {
        const int og = tid & 127;
        const int th = tid >> 7;
        const int t0 = th * 16;
        ull a0[8], a1[8];
        #pragma unroll
        for (int p = 0; p < 8; p++) { a0[p] = 0ULL; a1[p] = 0ULL; }

        for (int c = 0; c < COUTC; c++) {
            float wa = g_d1wt[c * COUTC + og];
            float wb = g_d1wt[c * COUTC + og + 128];
            ull wap = pk2(wa, wa), wbp = pk2(wb, wb);
            const ull* sp = (const ull*)(bufA + c * BSTR + t0);
            #pragma unroll
            for (int p = 0; p < 8; p++) {
                ull s = sp[p];
                a0[p] = fma2(wap, s, a0[p]);
                a1[p] = fma2(wbp, s, a1[p]);
            }
        }
        ull* d0 = (ull*)(zin + og * BSTR + t0);
        ull* d1 = (ull*)(zin + (og + 128) * BSTR + t0);
        #pragma unroll
        for (int p = 0; p < 8; p++) { d0[p] = a0[p]; d1[p] = a1[p]; }
    }
    __syncthreads();

    // ---- dense1 CUBA LIF: thr 0.1, cd=1, vd=0.1 ----
    if (tid < COUTC) {
        float* row = zin + tid * BSTR;
        const float vdD = (float)(1.0 - 0.1);
        float vol = 0.0f;
        #pragma unroll 1
        for (int t = 0; t < TT; t++) {
            float xv = row[t];
            vol = fmaf(vdD, vol, xv);
            float s = ((vol - 0.1f) >= 0.0f) ? 1.0f : 0.0f;
            row[t] = s;
            vol = vol * (1.0f - s);
        }
    }
    __syncthreads();

    // ---- dense2: [2 x 256] ----
    if (tid < NCLS * TT) {
        int cls = tid / TT, t = tid - cls * TT;
        const float* w = d2w + cls * COUTC;
        float a = 0.0f;
        #pragma unroll 4
        for (int c = 0; c < COUTC; c++) a = fmaf(w[c], zin[c * BSTR + t], a);
        bufA[tid] = a;
    }
    __syncthreads();

    // ---- dense2 CUBA LIF + output ----
    if (tid < NCLS) {
        const float vdD = (float)(1.0 - 0.1);
        float vol = 0.0f;
        const float* rowi = bufA + tid * TT;
        float* rowo = out + (size_t)n * (NCLS * TT) + tid * TT;
        #pragma unroll 1
        for (int t = 0; t < TT; t++) {
            float xv = rowi[t];
            vol = fmaf(vdD, vol, xv);
            float s = ((vol - 0.1f) >= 0.0f) ? 1.0f : 0.0f;
            rowo[t] = s;
            vol = vol * (1.0f - s);
        }
    }
}

// ---------------- launch ----------------
extern "C" void kernel_launch(void* const* d_in, const int* in_sizes, int n_in,
                              void* d_out, int out_size)
{
    const float* x    = (const float*)d_in[0];
    const float* c1w  = (const float*)d_in[1];
    const float* c1b  = (const float*)d_in[2];
    const float* bn1g = (const float*)d_in[3];
    const float* bn1b = (const float*)d_in[4];
    const float* bn1m = (const float*)d_in[5];
    const float* bn1v = (const float*)d_in[6];
    const float* c2w  = (const float*)d_in[7];
    const float* c2b  = (const float*)d_in[8];
    const float* bn2g = (const float*)d_in[9];
    const float* bn2b = (const float*)d_in[10];
    const float* bn2m = (const float*)d_in[11];
    const float* bn2v = (const float*)d_in[12];
    const float* d1w  = (const float*)d_in[13];
    const float* d2w  = (const float*)d_in[14];
    float* out = (float*)d_out;

    const int smem_bytes = (ZROWS * COUTC + COUTC * BSTR) * (int)sizeof(float);
    cudaFuncSetAttribute(mega_kernel, cudaFuncAttributeMaxDynamicSharedMemorySize, smem_bytes);

    prep_kernel<<<2048, 256>>>(c1w, c2w, d1w, bn1g, bn1v, bn2g, bn2v);

    dim3 g1(252, 2);
    conv1_gemm<<<g1, 256>>>(x, c1b, bn1b, bn1m);

    mega_kernel<<<BATCH, 512, smem_bytes>>>(c2b, bn2b, bn2m, d2w, out);
}